// round 12
// baseline (speedup 1.0000x reference)
#include <cuda_runtime.h>
#include <cuda_fp16.h>
#include <cstdint>
#include <math.h>

// Problem constants
#define BATCH   16
#define CC      192
#define NHEAD   6
#define NTOK    64
#define NWIN    64
#define MROWS   65536
#define QKVDIM  576
#define MLPDIM  768
#define SCALE_Q 0.17677669529663687f

// Weight half-buffer offsets (elements)
#define WOFF_QKV  0
#define WOFF_PROJ 221184
#define WOFF_FC1  294912
#define WOFF_FC2  589824
#define WTOTAL    884736

// Scratch (device globals)
__device__ __half g_ah[(size_t)MROWS * 192];
__device__ __half g_al[(size_t)MROWS * 192];
__device__ __half g_bh[(size_t)MROWS * 768];
__device__ __half g_bl[(size_t)MROWS * 768];
__device__ __half g_wh[WTOTAL];
__device__ __half g_wl[WTOTAL];

// ---------------------------------------------------------------------------
// PTX helpers
// ---------------------------------------------------------------------------
__device__ __forceinline__ uint32_t smem_u32(const void* p) {
    uint32_t a;
    asm("{ .reg .u64 t; cvta.to.shared.u64 t, %1; cvt.u32.u64 %0, t; }"
        : "=r"(a) : "l"(p));
    return a;
}

#define CP16(dst, src) \
    asm volatile("cp.async.cg.shared.global [%0], [%1], 16;" :: "r"(dst), "l"(src))

#define LDSM4(r0, r1, r2, r3, addr) \
    asm volatile("ldmatrix.sync.aligned.m8n8.x4.shared.b16 {%0,%1,%2,%3}, [%4];" \
        : "=r"(r0), "=r"(r1), "=r"(r2), "=r"(r3) : "r"(addr))

#define LDSM4T(r0, r1, r2, r3, addr) \
    asm volatile("ldmatrix.sync.aligned.m8n8.x4.trans.shared.b16 {%0,%1,%2,%3}, [%4];" \
        : "=r"(r0), "=r"(r1), "=r"(r2), "=r"(r3) : "r"(addr))

#define MMA16816(d, a, b0, b1) \
    asm volatile("mma.sync.aligned.m16n8k16.row.col.f32.f16.f16.f32 " \
        "{%0,%1,%2,%3},{%4,%5,%6,%7},{%8,%9},{%0,%1,%2,%3};" \
        : "+f"((d)[0]), "+f"((d)[1]), "+f"((d)[2]), "+f"((d)[3]) \
        : "r"((a)[0]), "r"((a)[1]), "r"((a)[2]), "r"((a)[3]), "r"(b0), "r"(b1))

#define MMA16816F16(d, a, b0, b1) \
    asm volatile("mma.sync.aligned.m16n8k16.row.col.f16.f16.f16.f16 " \
        "{%0,%1},{%2,%3,%4,%5},{%6,%7},{%0,%1};" \
        : "+r"((d)[0]), "+r"((d)[1]) \
        : "r"((a)[0]), "r"((a)[1]), "r"((a)[2]), "r"((a)[3]), "r"(b0), "r"(b1))

__device__ __forceinline__ uint32_t pack_hi(float x, float y) {
    __half2 h = __halves2half2(__float2half(x), __float2half(y));
    return *(uint32_t*)&h;
}
__device__ __forceinline__ uint32_t pack_lo(float x, float y) {
    __half hx = __float2half(x), hy = __float2half(y);
    __half2 h = __halves2half2(__float2half(x - __half2float(hx)),
                               __float2half(y - __half2float(hy)));
    return *(uint32_t*)&h;
}

// ---------------------------------------------------------------------------
// Weight conversion: two fp32 arrays -> (hi, lo) fp16, one kernel
// ---------------------------------------------------------------------------
__global__ __launch_bounds__(256) void cvt2_kernel(
    const float* __restrict__ s1, __half* __restrict__ h1, __half* __restrict__ l1, int n1,
    const float* __restrict__ s2, __half* __restrict__ h2, __half* __restrict__ l2, int n2)
{
    int i = blockIdx.x * 256 + threadIdx.x;
    const float* s; __half *h, *l; int j;
    if (i < n1) { s = s1; h = h1; l = l1; j = i; }
    else if (i < n1 + n2) { s = s2; h = h2; l = l2; j = i - n1; }
    else return;
    float x = s[j];
    __half hh = __float2half(x);
    h[j] = hh;
    l[j] = __float2half(x - __half2float(hh));
}

// ---------------------------------------------------------------------------
// LayerNorm (+ optional shift + window partition), outputs hi/lo fp16
// ---------------------------------------------------------------------------
__global__ __launch_bounds__(256) void ln_kernel(
    const float* __restrict__ x, const float* __restrict__ gam,
    const float* __restrict__ bet, __half* __restrict__ oh,
    __half* __restrict__ ol, int shift, int windowed)
{
    int warp = threadIdx.x >> 5, lane = threadIdx.x & 31;
    int r = blockIdx.x * 8 + warp;
    int src;
    if (windowed) {
        int bw = r >> 6, tok = r & 63;
        int b_img = bw >> 6, wr = (bw >> 3) & 7, wc = bw & 7;
        int ti = tok >> 3, tj = tok & 7;
        int h = (wr * 8 + ti + shift) & 63;
        int w = (wc * 8 + tj + shift) & 63;
        src = b_img * 4096 + h * 64 + w;
    } else src = r;
    const float* xp = x + (size_t)src * CC;
    float v[6];
    float s = 0.f;
#pragma unroll
    for (int j = 0; j < 6; j++) { v[j] = xp[lane + 32 * j]; s += v[j]; }
#pragma unroll
    for (int o = 16; o; o >>= 1) s += __shfl_xor_sync(0xffffffffu, s, o);
    float mu = s * (1.f / 192.f);
    float q = 0.f;
#pragma unroll
    for (int j = 0; j < 6; j++) { float d = v[j] - mu; q += d * d; }
#pragma unroll
    for (int o = 16; o; o >>= 1) q += __shfl_xor_sync(0xffffffffu, q, o);
    float rstd = rsqrtf(q * (1.f / 192.f) + 1e-5f);
    size_t base = (size_t)r * CC;
#pragma unroll
    for (int j = 0; j < 6; j++) {
        int c = lane + 32 * j;
        float y = (v[j] - mu) * rstd * gam[c] + bet[c];
        __half hh = __float2half(y);
        oh[base + c] = hh;
        ol[base + c] = __float2half(y - __half2float(hh));
    }
}

// ---------------------------------------------------------------------------
// Heterogeneous GEMM: C[M,N] = A[M,K] @ W[N,K]^T + bias.
// Blocks with (blockIdx.y % 4 == 3) run a SIMT fp32 SGEMM (fma pipe,
// reconstructing a = hi + lo); other blocks run the proven 3-term fp16-split
// tensor path. Interleaved by bid so both kinds co-reside per SM.
// ---------------------------------------------------------------------------
#define MODE_QKV     0
#define MODE_GELU_HL 1
#define MODE_RESADD  2
#define MODE_PROJ    3

#define STAGE_BYTES 49152
#define GEMM_SMEM   (2 * STAGE_BYTES)
// SIMT fp32 tiles: As[64][132] @0 (33792B), Bs[64][68] @33792 (17408B)

template<int MODE>
__device__ __forceinline__ void epilogue_pair(
    int r, int dest, int c, float v0, float v1,
    float* Cp, __half* Oh, __half* Ol, const float* Rsrc, int N)
{
    if (MODE == MODE_QKV) {
        if (c < 192) { v0 *= SCALE_Q; v1 *= SCALE_Q; }
        __half h0 = __float2half(v0), h1 = __float2half(v1);
        *(__half2*)(Oh + (size_t)r * N + c) = __halves2half2(h0, h1);
        *(__half2*)(Ol + (size_t)r * N + c) = __halves2half2(
            __float2half(v0 - __half2float(h0)),
            __float2half(v1 - __half2float(h1)));
    } else if (MODE == MODE_GELU_HL) {
        float g0 = 0.5f * v0 * (1.f + erff(v0 * 0.70710678118654752f));
        float g1 = 0.5f * v1 * (1.f + erff(v1 * 0.70710678118654752f));
        __half h0 = __float2half(g0), h1 = __float2half(g1);
        *(__half2*)(Oh + (size_t)r * N + c) = __halves2half2(h0, h1);
        *(__half2*)(Ol + (size_t)r * N + c) = __halves2half2(
            __float2half(g0 - __half2float(h0)),
            __float2half(g1 - __half2float(h1)));
    } else if (MODE == MODE_RESADD) {
        float2* p = (float2*)(Cp + (size_t)r * N + c);
        float2 o = *p; o.x += v0; o.y += v1; *p = o;
    } else { // MODE_PROJ
        float2 rv = *(const float2*)(Rsrc + (size_t)dest * CC + c);
        float2 o; o.x = rv.x + v0; o.y = rv.y + v1;
        *(float2*)(Cp + (size_t)dest * CC + c) = o;
    }
}

__device__ __forceinline__ int proj_dest(int r, int shift) {
    int bw = r >> 6, tok = r & 63;
    int b_img = bw >> 6, wr = (bw >> 3) & 7, wc = bw & 7;
    int ti = tok >> 3, tj = tok & 7;
    int h = (wr * 8 + ti + shift) & 63;
    int w = (wc * 8 + tj + shift) & 63;
    return b_img * 4096 + h * 64 + w;
}

template<int MODE>
__global__ __launch_bounds__(256, 2) void gemm_mma(
    const __half* __restrict__ Ah, const __half* __restrict__ Al,
    const __half* __restrict__ Bh, const __half* __restrict__ Bl,
    const float* __restrict__ bias, float* __restrict__ Cp,
    __half* __restrict__ Oh, __half* __restrict__ Ol,
    const float* __restrict__ Rsrc,
    int N, int K, int shift)
{
    extern __shared__ char smem[];
    const int tid  = threadIdx.x;
    const int m0 = blockIdx.y * 128, n0 = blockIdx.x * 64;
    const int niter = K >> 6;

    if ((blockIdx.y & 3) == 3) {
        // ------------------- SIMT fp32 path (fma pipe) -------------------
        float* As = (float*)smem;                  // [64][132]
        float* Bs = (float*)(smem + 33792);        // [64][68]
        const int tx = tid & 15, ty = tid >> 4;
        const int ar = tid >> 1, akb = (tid & 1) * 32;
        const int brn = tid >> 2, bkb = (tid & 3) * 16;
        const __half* pAh2 = Ah + (size_t)(m0 + ar) * K + akb;
        const __half* pAl2 = Al + (size_t)(m0 + ar) * K + akb;
        const __half* pBh2 = Bh + (size_t)(n0 + brn) * K + bkb;
        const __half* pBl2 = Bl + (size_t)(n0 + brn) * K + bkb;

        float acc[8][4];
#pragma unroll
        for (int i = 0; i < 8; i++)
#pragma unroll
            for (int j = 0; j < 4; j++) acc[i][j] = 0.f;

        for (int s = 0; s < niter; s++) {
            int k0 = s << 6;
            __syncthreads();
            // stage A (reconstruct fp32 = hi + lo) into [k][m]
#pragma unroll
            for (int q = 0; q < 4; q++) {
                uint4 hv = *(const uint4*)(pAh2 + k0 + q * 8);
                uint4 lv = *(const uint4*)(pAl2 + k0 + q * 8);
                const __half2* hp = (const __half2*)&hv;
                const __half2* lp = (const __half2*)&lv;
#pragma unroll
                for (int p = 0; p < 4; p++) {
                    float2 f = __half22float2(hp[p]);
                    float2 g = __half22float2(lp[p]);
                    int kk = akb + q * 8 + p * 2;
                    As[kk * 132 + ar]       = f.x + g.x;
                    As[(kk + 1) * 132 + ar] = f.y + g.y;
                }
            }
            // stage B into [k][n]
#pragma unroll
            for (int q = 0; q < 2; q++) {
                uint4 hv = *(const uint4*)(pBh2 + k0 + q * 8);
                uint4 lv = *(const uint4*)(pBl2 + k0 + q * 8);
                const __half2* hp = (const __half2*)&hv;
                const __half2* lp = (const __half2*)&lv;
#pragma unroll
                for (int p = 0; p < 4; p++) {
                    float2 f = __half22float2(hp[p]);
                    float2 g = __half22float2(lp[p]);
                    int kk = bkb + q * 8 + p * 2;
                    Bs[kk * 68 + brn]       = f.x + g.x;
                    Bs[(kk + 1) * 68 + brn] = f.y + g.y;
                }
            }
            __syncthreads();
#pragma unroll 8
            for (int kk = 0; kk < 64; kk++) {
                float4 a0 = *(const float4*)&As[kk * 132 + ty * 8];
                float4 a1 = *(const float4*)&As[kk * 132 + ty * 8 + 4];
                float4 b  = *(const float4*)&Bs[kk * 68 + tx * 4];
                float av[8] = {a0.x, a0.y, a0.z, a0.w, a1.x, a1.y, a1.z, a1.w};
                float bv[4] = {b.x, b.y, b.z, b.w};
#pragma unroll
                for (int i = 0; i < 8; i++)
#pragma unroll
                    for (int j = 0; j < 4; j++)
                        acc[i][j] += av[i] * bv[j];
            }
        }
        // epilogue
#pragma unroll
        for (int i = 0; i < 8; i++) {
            int r = m0 + ty * 8 + i;
            int dest = (MODE == MODE_PROJ) ? proj_dest(r, shift) : r;
#pragma unroll
            for (int j = 0; j < 4; j += 2) {
                int c = n0 + tx * 4 + j;
                epilogue_pair<MODE>(r, dest, c,
                    acc[i][j] + bias[c], acc[i][j + 1] + bias[c + 1],
                    Cp, Oh, Ol, Rsrc, N);
            }
        }
        return;
    }

    // ------------------- tensor 3-term split path (R11) -------------------
    const uint32_t smbase = smem_u32(smem);
    const int lane = tid & 31, warp = tid >> 5;
    const int wm = warp >> 1, wn = warp & 1;
    const int lc = tid & 7;
    const int lr = tid >> 3;

    const __half* pAh = Ah + (size_t)m0 * K + lc * 8;
    const __half* pAl = Al + (size_t)m0 * K + lc * 8;
    const __half* pBh = Bh + (size_t)n0 * K + lc * 8;
    const __half* pBl = Bl + (size_t)n0 * K + lc * 8;

    auto issue = [&](int s) {
        uint32_t sb = smbase + (uint32_t)(s & 1) * STAGE_BYTES;
        int k0 = s << 6;
#pragma unroll
        for (int i = 0; i < 4; i++) {
            int r = lr + 32 * i;
            uint32_t d = sb + r * 128 + ((uint32_t)(lc ^ (r & 7)) << 4);
            CP16(d,         pAh + (size_t)r * K + k0);
            CP16(d + 16384, pAl + (size_t)r * K + k0);
        }
#pragma unroll
        for (int i = 0; i < 2; i++) {
            int r = lr + 32 * i;
            uint32_t d = sb + 32768 + r * 128 + ((uint32_t)(lc ^ (r & 7)) << 4);
            CP16(d,        pBh + (size_t)r * K + k0);
            CP16(d + 8192, pBl + (size_t)r * K + k0);
        }
        asm volatile("cp.async.commit_group;");
    };

    float acc[2][4][4];
    uint32_t cac[2][4][2];
#pragma unroll
    for (int i = 0; i < 2; i++)
#pragma unroll
        for (int j = 0; j < 4; j++) {
#pragma unroll
            for (int e = 0; e < 4; e++) acc[i][j][e] = 0.f;
            cac[i][j][0] = 0u; cac[i][j][1] = 0u;
        }

    issue(0);
    for (int s = 0; s < niter; s++) {
        if (s + 1 < niter) {
            issue(s + 1);
            asm volatile("cp.async.wait_group 1;");
        } else {
            asm volatile("cp.async.wait_group 0;");
        }
        __syncthreads();
        uint32_t sb = smbase + (uint32_t)(s & 1) * STAGE_BYTES;
#pragma unroll
        for (int kk = 0; kk < 4; kk++) {
            uint32_t aH[2][4], aL[2][4], bH[2][4], bL[2][4];
#pragma unroll
            for (int i = 0; i < 2; i++) {
                int r  = wm * 32 + i * 16 + (lane & 15);
                int ch = kk * 2 + (lane >> 4);
                uint32_t ad = sb + r * 128 + ((uint32_t)(ch ^ (r & 7)) << 4);
                LDSM4(aH[i][0], aH[i][1], aH[i][2], aH[i][3], ad);
                LDSM4(aL[i][0], aL[i][1], aL[i][2], aL[i][3], ad + 16384);
            }
#pragma unroll
            for (int i = 0; i < 2; i++) {
                int grp = lane >> 3;
                int r  = wn * 32 + i * 16 + ((grp >> 1) << 3) + (lane & 7);
                int ch = kk * 2 + (grp & 1);
                uint32_t bd = sb + 32768 + r * 128 + ((uint32_t)(ch ^ (r & 7)) << 4);
                LDSM4(bH[i][0], bH[i][1], bH[i][2], bH[i][3], bd);
                LDSM4(bL[i][0], bL[i][1], bL[i][2], bL[i][3], bd + 8192);
            }
#pragma unroll
            for (int i = 0; i < 2; i++)
#pragma unroll
                for (int jj = 0; jj < 4; jj++) {
                    int bi = jj >> 1, bo = (jj & 1) * 2;
                    MMA16816(acc[i][jj], aH[i], bH[bi][bo], bH[bi][bo + 1]);
                }
#pragma unroll
            for (int i = 0; i < 2; i++)
#pragma unroll
                for (int jj = 0; jj < 4; jj++) {
                    int bi = jj >> 1, bo = (jj & 1) * 2;
                    MMA16816F16(cac[i][jj], aH[i], bL[bi][bo], bL[bi][bo + 1]);
                }
#pragma unroll
            for (int i = 0; i < 2; i++)
#pragma unroll
                for (int jj = 0; jj < 4; jj++) {
                    int bi = jj >> 1, bo = (jj & 1) * 2;
                    MMA16816F16(cac[i][jj], aL[i], bH[bi][bo], bH[bi][bo + 1]);
                }
        }
        __syncthreads();
    }

#pragma unroll
    for (int i = 0; i < 2; i++) {
        int rb = m0 + wm * 32 + i * 16 + (lane >> 2);
#pragma unroll
        for (int hf = 0; hf < 2; hf++) {
            int r = rb + hf * 8;
            int dest = (MODE == MODE_PROJ) ? proj_dest(r, shift) : r;
#pragma unroll
            for (int jj = 0; jj < 4; jj++) {
                int c = n0 + wn * 32 + jj * 8 + (lane & 3) * 2;
                __half2 corr = *(__half2*)&cac[i][jj][hf];
                epilogue_pair<MODE>(r, dest, c,
                    acc[i][jj][hf * 2 + 0] + __low2float(corr)  + bias[c],
                    acc[i][jj][hf * 2 + 1] + __high2float(corr) + bias[c + 1],
                    Cp, Oh, Ol, Rsrc, N);
            }
        }
    }
}

// ---------------------------------------------------------------------------
// Tensor-core windowed attention: one CTA = 2 heads (128 threads, 4 warps).
// ---------------------------------------------------------------------------
struct __align__(16) AttnSmem2 {
    __half qh[2][2048], ql[2][2048];
    __half kh[2][2048], kl[2][2048];
    __half vh[2][2048], vl[2][2048];
    float  tbl[2][225];
    unsigned char rel[4096];
    int    rid[64];
};
#define ATTN_SMEM ((int)sizeof(AttnSmem2))

__global__ __launch_bounds__(128) void attn_mma(
    const __half* __restrict__ Qh, const __half* __restrict__ Ql,
    const float* __restrict__ tblg,
    __half* __restrict__ oh, __half* __restrict__ ol, int shift)
{
    extern __shared__ char smraw[];
    AttnSmem2& sm = *reinterpret_cast<AttnSmem2*>(smraw);
    int bw = blockIdx.y;
    int tid = threadIdx.x;
    int sub = tid >> 6, t64 = tid & 63;
    int lane = tid & 31, wq = (t64 >> 5);
    int head = blockIdx.x * 2 + sub;

    __half* bufs[6] = {sm.qh[sub], sm.ql[sub], sm.kh[sub], sm.kl[sub],
                       sm.vh[sub], sm.vl[sub]};
#pragma unroll
    for (int it = 0; it < 24; it++) {
        int idx = t64 + it * 64;
        int buf = idx >> 8, rem = idx & 255, r = rem >> 2, ch = rem & 3;
        int sec = buf >> 1;
        const __half* src = (buf & 1) ? Ql : Qh;
        const __half* p = src + (size_t)(bw * 64 + r) * QKVDIM + sec * 192 + head * 32 + ch * 8;
        uint4 val = *(const uint4*)p;
        *(uint4*)((char*)bufs[buf] + r * 64 + ((ch ^ (r & 3)) << 4)) = val;
    }
    for (int idx = tid; idx < 4096; idx += 128) {
        int n = idx >> 6, m = idx & 63;
        sm.rel[idx] = (unsigned char)(((n >> 3) - (m >> 3) + 7) * 15 + ((n & 7) - (m & 7) + 7));
    }
    for (int idx = t64; idx < 225; idx += 64) sm.tbl[sub][idx] = tblg[idx * NHEAD + head];
    if (tid < 64) {
        int wr = (bw >> 3) & 7, wc = bw & 7;
        int ti = tid >> 3, tj = tid & 7;
        int h = wr * 8 + ti, w = wc * 8 + tj;
        int rh = (h < 56) ? 0 : ((h < 60) ? 1 : 2);
        int rw = (w < 56) ? 0 : ((w < 60) ? 1 : 2);
        sm.rid[tid] = rh * 3 + rw;
    }
    __syncthreads();

    uint32_t qhb = smem_u32(sm.qh[sub]), qlb = smem_u32(sm.ql[sub]);
    uint32_t khb = smem_u32(sm.kh[sub]), klb = smem_u32(sm.kl[sub]);
    uint32_t vhb = smem_u32(sm.vh[sub]), vlb = smem_u32(sm.vl[sub]);

    float sc[2][8][4];
#pragma unroll
    for (int i = 0; i < 2; i++)
#pragma unroll
        for (int j = 0; j < 8; j++)
#pragma unroll
            for (int e = 0; e < 4; e++) sc[i][j][e] = 0.f;

#pragma unroll
    for (int kk = 0; kk < 2; kk++) {
        uint32_t aH[2][4], aL[2][4], bH[4][4], bL[4][4];
#pragma unroll
        for (int i = 0; i < 2; i++) {
            int r  = wq * 32 + i * 16 + (lane & 15);
            int ch = kk * 2 + (lane >> 4);
            uint32_t off = (uint32_t)(r * 64 + ((ch ^ (r & 3)) << 4));
            LDSM4(aH[i][0], aH[i][1], aH[i][2], aH[i][3], qhb + off);
            LDSM4(aL[i][0], aL[i][1], aL[i][2], aL[i][3], qlb + off);
        }
#pragma unroll
        for (int i = 0; i < 4; i++) {
            int grp = lane >> 3;
            int r  = i * 16 + ((grp >> 1) << 3) + (lane & 7);
            int ch = kk * 2 + (grp & 1);
            uint32_t off = (uint32_t)(r * 64 + ((ch ^ (r & 3)) << 4));
            LDSM4(bH[i][0], bH[i][1], bH[i][2], bH[i][3], khb + off);
            LDSM4(bL[i][0], bL[i][1], bL[i][2], bL[i][3], klb + off);
        }
#pragma unroll
        for (int i = 0; i < 2; i++)
#pragma unroll
            for (int j = 0; j < 8; j++) {
                int bi = j >> 1, bo = (j & 1) * 2;
                MMA16816(sc[i][j], aH[i], bH[bi][bo], bH[bi][bo + 1]);
            }
#pragma unroll
        for (int i = 0; i < 2; i++)
#pragma unroll
            for (int j = 0; j < 8; j++) {
                int bi = j >> 1, bo = (j & 1) * 2;
                MMA16816(sc[i][j], aH[i], bL[bi][bo], bL[bi][bo + 1]);
            }
#pragma unroll
        for (int i = 0; i < 2; i++)
#pragma unroll
            for (int j = 0; j < 8; j++) {
                int bi = j >> 1, bo = (j & 1) * 2;
                MMA16816(sc[i][j], aL[i], bH[bi][bo], bH[bi][bo + 1]);
            }
    }

    int gr = lane >> 2, lam = lane & 3;
    float invs[2][2];
#pragma unroll
    for (int i = 0; i < 2; i++) {
        int rA = wq * 32 + i * 16 + gr, rB = rA + 8;
        int ridA = sm.rid[rA], ridB = sm.rid[rB];
        float mxA = -1e30f, mxB = -1e30f;
#pragma unroll
        for (int j = 0; j < 8; j++) {
            int c0 = 8 * j + 2 * lam;
            float b00 = sm.tbl[sub][sm.rel[rA * 64 + c0]];
            float b01 = sm.tbl[sub][sm.rel[rA * 64 + c0 + 1]];
            float b10 = sm.tbl[sub][sm.rel[rB * 64 + c0]];
            float b11 = sm.tbl[sub][sm.rel[rB * 64 + c0 + 1]];
            if (shift) {
                int rc0 = sm.rid[c0], rc1 = sm.rid[c0 + 1];
                if (rc0 != ridA) b00 -= 100.f;
                if (rc1 != ridA) b01 -= 100.f;
                if (rc0 != ridB) b10 -= 100.f;
                if (rc1 != ridB) b11 -= 100.f;
            }
            sc[i][j][0] += b00; sc[i][j][1] += b01;
            sc[i][j][2] += b10; sc[i][j][3] += b11;
            mxA = fmaxf(mxA, fmaxf(sc[i][j][0], sc[i][j][1]));
            mxB = fmaxf(mxB, fmaxf(sc[i][j][2], sc[i][j][3]));
        }
        mxA = fmaxf(mxA, __shfl_xor_sync(0xffffffffu, mxA, 1));
        mxA = fmaxf(mxA, __shfl_xor_sync(0xffffffffu, mxA, 2));
        mxB = fmaxf(mxB, __shfl_xor_sync(0xffffffffu, mxB, 1));
        mxB = fmaxf(mxB, __shfl_xor_sync(0xffffffffu, mxB, 2));
        float sA = 0.f, sB = 0.f;
#pragma unroll
        for (int j = 0; j < 8; j++) {
            sc[i][j][0] = __expf(sc[i][j][0] - mxA); sA += sc[i][j][0];
            sc[i][j][1] = __expf(sc[i][j][1] - mxA); sA += sc[i][j][1];
            sc[i][j][2] = __expf(sc[i][j][2] - mxB); sB += sc[i][j][2];
            sc[i][j][3] = __expf(sc[i][j][3] - mxB); sB += sc[i][j][3];
        }
        sA += __shfl_xor_sync(0xffffffffu, sA, 1);
        sA += __shfl_xor_sync(0xffffffffu, sA, 2);
        sB += __shfl_xor_sync(0xffffffffu, sB, 1);
        sB += __shfl_xor_sync(0xffffffffu, sB, 2);
        invs[i][0] = 1.f / sA;
        invs[i][1] = 1.f / sB;
    }

    float out[2][4][4];
#pragma unroll
    for (int i = 0; i < 2; i++)
#pragma unroll
        for (int j = 0; j < 4; j++)
#pragma unroll
            for (int e = 0; e < 4; e++) out[i][j][e] = 0.f;

#pragma unroll
    for (int kv = 0; kv < 4; kv++) {
        uint32_t vH[2][4], vL[2][4];
#pragma unroll
        for (int dn = 0; dn < 2; dn++) {
            int r  = kv * 16 + (lane & 7) + (((lane >> 3) & 1) << 3);
            int ch = dn * 2 + (lane >> 4);
            uint32_t off = (uint32_t)(r * 64 + ((ch ^ (r & 3)) << 4));
            LDSM4T(vH[dn][0], vH[dn][1], vH[dn][2], vH[dn][3], vhb + off);
            LDSM4T(vL[dn][0], vL[dn][1], vL[dn][2], vL[dn][3], vlb + off);
        }
#pragma unroll
        for (int i = 0; i < 2; i++) {
            uint32_t pH[4], pL[4];
            pH[0] = pack_hi(sc[i][2 * kv][0], sc[i][2 * kv][1]);
            pH[1] = pack_hi(sc[i][2 * kv][2], sc[i][2 * kv][3]);
            pH[2] = pack_hi(sc[i][2 * kv + 1][0], sc[i][2 * kv + 1][1]);
            pH[3] = pack_hi(sc[i][2 * kv + 1][2], sc[i][2 * kv + 1][3]);
            pL[0] = pack_lo(sc[i][2 * kv][0], sc[i][2 * kv][1]);
            pL[1] = pack_lo(sc[i][2 * kv][2], sc[i][2 * kv][3]);
            pL[2] = pack_lo(sc[i][2 * kv + 1][0], sc[i][2 * kv + 1][1]);
            pL[3] = pack_lo(sc[i][2 * kv + 1][2], sc[i][2 * kv + 1][3]);
#pragma unroll
            for (int dt = 0; dt < 4; dt++) {
                int bi = dt >> 1, bo = (dt & 1) * 2;
                MMA16816(out[i][dt], pH, vH[bi][bo], vH[bi][bo + 1]);
            }
#pragma unroll
            for (int dt = 0; dt < 4; dt++) {
                int bi = dt >> 1, bo = (dt & 1) * 2;
                MMA16816(out[i][dt], pH, vL[bi][bo], vL[bi][bo + 1]);
            }
#pragma unroll
            for (int dt = 0; dt < 4; dt++) {
                int bi = dt >> 1, bo = (dt & 1) * 2;
                MMA16816(out[i][dt], pL, vH[bi][bo], vH[bi][bo + 1]);
            }
        }
    }

#pragma unroll
    for (int i = 0; i < 2; i++) {
        int rA = wq * 32 + i * 16 + gr;
#pragma unroll
        for (int hf = 0; hf < 2; hf++) {
            int r = rA + hf * 8;
            float inv = invs[i][hf];
            size_t base = (size_t)(bw * 64 + r) * 192 + head * 32;
#pragma unroll
            for (int dt = 0; dt < 4; dt++) {
                int c = 8 * dt + 2 * lam;
                float v0 = out[i][dt][hf * 2 + 0] * inv;
                float v1 = out[i][dt][hf * 2 + 1] * inv;
                __half h0 = __float2half(v0), h1 = __float2half(v1);
                *(__half2*)(oh + base + c) = __halves2half2(h0, h1);
                *(__half2*)(ol + base + c) = __halves2half2(
                    __float2half(v0 - __half2float(h0)),
                    __float2half(v1 - __half2float(h1)));
            }
        }
    }
}

// ---------------------------------------------------------------------------
// Launch
// ---------------------------------------------------------------------------
extern "C" void kernel_launch(void* const* d_in, const int* in_sizes, int n_in,
                              void* d_out, int out_size)
{
    const float* x    = (const float*)d_in[0];
    const float* n1g  = (const float*)d_in[1];
    const float* n1b  = (const float*)d_in[2];
    const float* qkvw = (const float*)d_in[3];
    const float* qkvb = (const float*)d_in[4];
    const float* tbl  = (const float*)d_in[5];
    const float* pw   = (const float*)d_in[6];
    const float* pb   = (const float*)d_in[7];
    const float* n2g  = (const float*)d_in[8];
    const float* n2b  = (const float*)d_in[9];
    const float* f1w  = (const float*)d_in[10];
    const float* f1b  = (const float*)d_in[11];
    const float* f2w  = (const float*)d_in[12];
    const float* f2b  = (const float*)d_in[13];
    float* xo = (float*)d_out;

    __half *ah, *al, *bh, *bl, *wh, *wl;
    cudaGetSymbolAddress((void**)&ah,  g_ah);
    cudaGetSymbolAddress((void**)&al,  g_al);
    cudaGetSymbolAddress((void**)&bh,  g_bh);
    cudaGetSymbolAddress((void**)&bl,  g_bl);
    cudaGetSymbolAddress((void**)&wh,  g_wh);
    cudaGetSymbolAddress((void**)&wl,  g_wl);

    cudaFuncSetAttribute(gemm_mma<MODE_QKV>,     cudaFuncAttributeMaxDynamicSharedMemorySize, GEMM_SMEM);
    cudaFuncSetAttribute(gemm_mma<MODE_GELU_HL>, cudaFuncAttributeMaxDynamicSharedMemorySize, GEMM_SMEM);
    cudaFuncSetAttribute(gemm_mma<MODE_RESADD>,  cudaFuncAttributeMaxDynamicSharedMemorySize, GEMM_SMEM);
    cudaFuncSetAttribute(gemm_mma<MODE_PROJ>,    cudaFuncAttributeMaxDynamicSharedMemorySize, GEMM_SMEM);
    cudaFuncSetAttribute(attn_mma,               cudaFuncAttributeMaxDynamicSharedMemorySize, ATTN_SMEM);

    cvt2_kernel<<<(221184 + 73728 + 255) / 256, 256>>>(
        qkvw, wh + WOFF_QKV, wl + WOFF_QKV, 221184,
        pw,   wh + WOFF_PROJ, wl + WOFF_PROJ, 73728);
    cvt2_kernel<<<(294912 + 294912 + 255) / 256, 256>>>(
        f1w, wh + WOFF_FC1, wl + WOFF_FC1, 294912,
        f2w, wh + WOFF_FC2, wl + WOFF_FC2, 294912);

    for (int dep = 0; dep < 2; dep++) {
        int shift = dep ? 4 : 0;
        const float* resid = dep ? (const float*)xo : x;
        const float* lnsrc = dep ? (const float*)xo : x;
        const __half* wqh = wh + WOFF_QKV  + (size_t)dep * 110592;
        const __half* wql = wl + WOFF_QKV  + (size_t)dep * 110592;
        const __half* wph = wh + WOFF_PROJ + (size_t)dep * 36864;
        const __half* wpl = wl + WOFF_PROJ + (size_t)dep * 36864;
        const __half* w1h = wh + WOFF_FC1  + (size_t)dep * 147456;
        const __half* w1l = wl + WOFF_FC1  + (size_t)dep * 147456;
        const __half* w2h = wh + WOFF_FC2  + (size_t)dep * 147456;
        const __half* w2l = wl + WOFF_FC2  + (size_t)dep * 147456;

        ln_kernel<<<MROWS / 8, 256>>>(lnsrc, n1g + dep * CC, n1b + dep * CC, ah, al, shift, 1);

        gemm_mma<MODE_QKV><<<dim3(QKVDIM / 64, MROWS / 128), 256, GEMM_SMEM>>>(
            ah, al, wqh, wql, qkvb + dep * QKVDIM, nullptr, bh, bl, nullptr,
            QKVDIM, CC, 0);

        attn_mma<<<dim3(NHEAD / 2, BATCH * NWIN), 128, ATTN_SMEM>>>(
            bh, bl, tbl + dep * 225 * NHEAD, ah, al, shift);

        gemm_mma<MODE_PROJ><<<dim3(CC / 64, MROWS / 128), 256, GEMM_SMEM>>>(
            ah, al, wph, wpl, pb + dep * CC, xo, nullptr, nullptr, resid,
            CC, CC, shift);

        ln_kernel<<<MROWS / 8, 256>>>(xo, n2g + dep * CC, n2b + dep * CC, ah, al, 0, 0);

        gemm_mma<MODE_GELU_HL><<<dim3(MLPDIM / 64, MROWS / 128), 256, GEMM_SMEM>>>(
            ah, al, w1h, w1l, f1b + dep * MLPDIM, nullptr, bh, bl, nullptr,
            MLPDIM, CC, 0);

        gemm_mma<MODE_RESADD><<<dim3(CC / 64, MROWS / 128), 256, GEMM_SMEM>>>(
            bh, bl, w2h, w2l, f2b + dep * CC, xo, nullptr, nullptr, nullptr,
            CC, MLPDIM, 0);
    }
}

// round 13
// speedup vs baseline: 1.9241x; 1.9241x over previous
#include <cuda_runtime.h>
#include <cuda_fp16.h>
#include <cstdint>
#include <math.h>

// Problem constants
#define BATCH   16
#define CC      192
#define NHEAD   6
#define NTOK    64
#define NWIN    64
#define MROWS   65536
#define QKVDIM  576
#define MLPDIM  768
#define SCALE_Q 0.17677669529663687f

// Weight half-buffer offsets (elements)
#define WOFF_QKV  0
#define WOFF_PROJ 221184
#define WOFF_FC1  294912
#define WOFF_FC2  589824
#define WTOTAL    884736

// Scratch (device globals)
__device__ __half g_ah[(size_t)MROWS * 192];   // activations hi (GEMM A inputs)
__device__ __half g_bh[(size_t)MROWS * 768];   // qkv / gelu hi
__device__ __half g_bl[(size_t)MROWS * 768];   // qkv lo (attention only)
__device__ __half g_wh[WTOTAL];
__device__ __half g_wl[WTOTAL];

// ---------------------------------------------------------------------------
// PTX helpers
// ---------------------------------------------------------------------------
__device__ __forceinline__ uint32_t smem_u32(const void* p) {
    uint32_t a;
    asm("{ .reg .u64 t; cvta.to.shared.u64 t, %1; cvt.u32.u64 %0, t; }"
        : "=r"(a) : "l"(p));
    return a;
}

#define CP16(dst, src) \
    asm volatile("cp.async.cg.shared.global [%0], [%1], 16;" :: "r"(dst), "l"(src))

#define LDSM4(r0, r1, r2, r3, addr) \
    asm volatile("ldmatrix.sync.aligned.m8n8.x4.shared.b16 {%0,%1,%2,%3}, [%4];" \
        : "=r"(r0), "=r"(r1), "=r"(r2), "=r"(r3) : "r"(addr))

#define LDSM4T(r0, r1, r2, r3, addr) \
    asm volatile("ldmatrix.sync.aligned.m8n8.x4.trans.shared.b16 {%0,%1,%2,%3}, [%4];" \
        : "=r"(r0), "=r"(r1), "=r"(r2), "=r"(r3) : "r"(addr))

#define MMA16816(d, a, b0, b1) \
    asm volatile("mma.sync.aligned.m16n8k16.row.col.f32.f16.f16.f32 " \
        "{%0,%1,%2,%3},{%4,%5,%6,%7},{%8,%9},{%0,%1,%2,%3};" \
        : "+f"((d)[0]), "+f"((d)[1]), "+f"((d)[2]), "+f"((d)[3]) \
        : "r"((a)[0]), "r"((a)[1]), "r"((a)[2]), "r"((a)[3]), "r"(b0), "r"(b1))

#define MMA16816F16(d, a, b0, b1) \
    asm volatile("mma.sync.aligned.m16n8k16.row.col.f16.f16.f16.f16 " \
        "{%0,%1},{%2,%3,%4,%5},{%6,%7},{%0,%1};" \
        : "+r"((d)[0]), "+r"((d)[1]) \
        : "r"((a)[0]), "r"((a)[1]), "r"((a)[2]), "r"((a)[3]), "r"(b0), "r"(b1))

__device__ __forceinline__ uint32_t pack_hi(float x, float y) {
    __half2 h = __halves2half2(__float2half(x), __float2half(y));
    return *(uint32_t*)&h;
}
__device__ __forceinline__ uint32_t pack_lo(float x, float y) {
    __half hx = __float2half(x), hy = __float2half(y);
    __half2 h = __halves2half2(__float2half(x - __half2float(hx)),
                               __float2half(y - __half2float(hy)));
    return *(uint32_t*)&h;
}

// ---------------------------------------------------------------------------
// Weight conversion: two fp32 arrays -> (hi, lo) fp16, one kernel
// ---------------------------------------------------------------------------
__global__ __launch_bounds__(256) void cvt2_kernel(
    const float* __restrict__ s1, __half* __restrict__ h1, __half* __restrict__ l1, int n1,
    const float* __restrict__ s2, __half* __restrict__ h2, __half* __restrict__ l2, int n2)
{
    int i = blockIdx.x * 256 + threadIdx.x;
    const float* s; __half *h, *l; int j;
    if (i < n1) { s = s1; h = h1; l = l1; j = i; }
    else if (i < n1 + n2) { s = s2; h = h2; l = l2; j = i - n1; }
    else return;
    float x = s[j];
    __half hh = __float2half(x);
    h[j] = hh;
    l[j] = __float2half(x - __half2float(hh));
}

// ---------------------------------------------------------------------------
// LayerNorm (+ optional shift + window partition) -> fp16 hi only
// ---------------------------------------------------------------------------
__global__ __launch_bounds__(256) void ln_kernel(
    const float* __restrict__ x, const float* __restrict__ gam,
    const float* __restrict__ bet, __half* __restrict__ oh,
    int shift, int windowed)
{
    int warp = threadIdx.x >> 5, lane = threadIdx.x & 31;
    int r = blockIdx.x * 8 + warp;
    int src;
    if (windowed) {
        int bw = r >> 6, tok = r & 63;
        int b_img = bw >> 6, wr = (bw >> 3) & 7, wc = bw & 7;
        int ti = tok >> 3, tj = tok & 7;
        int h = (wr * 8 + ti + shift) & 63;
        int w = (wc * 8 + tj + shift) & 63;
        src = b_img * 4096 + h * 64 + w;
    } else src = r;
    const float* xp = x + (size_t)src * CC;
    float v[6];
    float s = 0.f;
#pragma unroll
    for (int j = 0; j < 6; j++) { v[j] = xp[lane + 32 * j]; s += v[j]; }
#pragma unroll
    for (int o = 16; o; o >>= 1) s += __shfl_xor_sync(0xffffffffu, s, o);
    float mu = s * (1.f / 192.f);
    float q = 0.f;
#pragma unroll
    for (int j = 0; j < 6; j++) { float d = v[j] - mu; q += d * d; }
#pragma unroll
    for (int o = 16; o; o >>= 1) q += __shfl_xor_sync(0xffffffffu, q, o);
    float rstd = rsqrtf(q * (1.f / 192.f) + 1e-5f);
    size_t base = (size_t)r * CC;
#pragma unroll
    for (int j = 0; j < 6; j++) {
        int c = lane + 32 * j;
        float y = (v[j] - mu) * rstd * gam[c] + bet[c];
        oh[base + c] = __float2half(y);
    }
}

// ---------------------------------------------------------------------------
// 2-term fp16-split tensor GEMM: C = A[M,K] @ W[N,K]^T + bias.
// main aH*bH (fp32 acc) + weight-lo correction aH*bL (f16 acc).
// Activation lo is not used. BM=128, BN=64, BK=64, 256 thr, 32x32 warp tile.
// ---------------------------------------------------------------------------
#define MODE_QKV     0   // writes hi AND lo (attention consumes both)
#define MODE_GELU_H  1   // writes hi only
#define MODE_RESADD  2
#define MODE_PROJ    3

// stage: Ah 16K @0, Bh 8K @16384, Bl 8K @24576
#define STAGE_BYTES 32768
#define GEMM_SMEM   (2 * STAGE_BYTES)

__device__ __forceinline__ int proj_dest(int r, int shift) {
    int bw = r >> 6, tok = r & 63;
    int b_img = bw >> 6, wr = (bw >> 3) & 7, wc = bw & 7;
    int ti = tok >> 3, tj = tok & 7;
    int h = (wr * 8 + ti + shift) & 63;
    int w = (wc * 8 + tj + shift) & 63;
    return b_img * 4096 + h * 64 + w;
}

template<int MODE>
__global__ __launch_bounds__(256, 2) void gemm_mma(
    const __half* __restrict__ Ah,
    const __half* __restrict__ Bh, const __half* __restrict__ Bl,
    const float* __restrict__ bias, float* __restrict__ Cp,
    __half* __restrict__ Oh, __half* __restrict__ Ol,
    const float* __restrict__ Rsrc,
    int N, int K, int shift)
{
    extern __shared__ char smem[];
    const uint32_t smbase = smem_u32(smem);
    const int tid  = threadIdx.x;
    const int lane = tid & 31, warp = tid >> 5;
    const int wm = warp >> 1, wn = warp & 1;
    const int m0 = blockIdx.y * 128, n0 = blockIdx.x * 64;
    const int lc = tid & 7;
    const int lr = tid >> 3;

    const __half* pAh = Ah + (size_t)m0 * K + lc * 8;
    const __half* pBh = Bh + (size_t)n0 * K + lc * 8;
    const __half* pBl = Bl + (size_t)n0 * K + lc * 8;

    const int niter = K >> 6;

    auto issue = [&](int s) {
        uint32_t sb = smbase + (uint32_t)(s & 1) * STAGE_BYTES;
        int k0 = s << 6;
#pragma unroll
        for (int i = 0; i < 4; i++) {
            int r = lr + 32 * i;
            uint32_t d = sb + r * 128 + ((uint32_t)(lc ^ (r & 7)) << 4);
            CP16(d, pAh + (size_t)r * K + k0);
        }
#pragma unroll
        for (int i = 0; i < 2; i++) {
            int r = lr + 32 * i;
            uint32_t d = sb + 16384 + r * 128 + ((uint32_t)(lc ^ (r & 7)) << 4);
            CP16(d,        pBh + (size_t)r * K + k0);
            CP16(d + 8192, pBl + (size_t)r * K + k0);
        }
        asm volatile("cp.async.commit_group;");
    };

    float acc[2][4][4];
    uint32_t cac[2][4][2];
#pragma unroll
    for (int i = 0; i < 2; i++)
#pragma unroll
        for (int j = 0; j < 4; j++) {
#pragma unroll
            for (int e = 0; e < 4; e++) acc[i][j][e] = 0.f;
            cac[i][j][0] = 0u; cac[i][j][1] = 0u;
        }

    issue(0);
    for (int s = 0; s < niter; s++) {
        if (s + 1 < niter) {
            issue(s + 1);
            asm volatile("cp.async.wait_group 1;");
        } else {
            asm volatile("cp.async.wait_group 0;");
        }
        __syncthreads();
        uint32_t sb = smbase + (uint32_t)(s & 1) * STAGE_BYTES;
#pragma unroll
        for (int kk = 0; kk < 4; kk++) {
            uint32_t aH[2][4], bH[2][4], bL[2][4];
#pragma unroll
            for (int i = 0; i < 2; i++) {
                int r  = wm * 32 + i * 16 + (lane & 15);
                int ch = kk * 2 + (lane >> 4);
                uint32_t ad = sb + r * 128 + ((uint32_t)(ch ^ (r & 7)) << 4);
                LDSM4(aH[i][0], aH[i][1], aH[i][2], aH[i][3], ad);
            }
#pragma unroll
            for (int i = 0; i < 2; i++) {
                int grp = lane >> 3;
                int r  = wn * 32 + i * 16 + ((grp >> 1) << 3) + (lane & 7);
                int ch = kk * 2 + (grp & 1);
                uint32_t bd = sb + 16384 + r * 128 + ((uint32_t)(ch ^ (r & 7)) << 4);
                LDSM4(bH[i][0], bH[i][1], bH[i][2], bH[i][3], bd);
                LDSM4(bL[i][0], bL[i][1], bL[i][2], bL[i][3], bd + 8192);
            }
#pragma unroll
            for (int i = 0; i < 2; i++)
#pragma unroll
                for (int jj = 0; jj < 4; jj++) {
                    int bi = jj >> 1, bo = (jj & 1) * 2;
                    MMA16816(acc[i][jj], aH[i], bH[bi][bo], bH[bi][bo + 1]);
                }
#pragma unroll
            for (int i = 0; i < 2; i++)
#pragma unroll
                for (int jj = 0; jj < 4; jj++) {
                    int bi = jj >> 1, bo = (jj & 1) * 2;
                    MMA16816F16(cac[i][jj], aH[i], bL[bi][bo], bL[bi][bo + 1]);
                }
        }
        __syncthreads();
    }

    // epilogue
#pragma unroll
    for (int i = 0; i < 2; i++) {
        int rb = m0 + wm * 32 + i * 16 + (lane >> 2);
#pragma unroll
        for (int hf = 0; hf < 2; hf++) {
            int r = rb + hf * 8;
            int dest = (MODE == MODE_PROJ) ? proj_dest(r, shift) : r;
#pragma unroll
            for (int jj = 0; jj < 4; jj++) {
                int c = n0 + wn * 32 + jj * 8 + (lane & 3) * 2;
                __half2 corr = *(__half2*)&cac[i][jj][hf];
                float v0 = acc[i][jj][hf * 2 + 0] + __low2float(corr)  + bias[c];
                float v1 = acc[i][jj][hf * 2 + 1] + __high2float(corr) + bias[c + 1];
                if (MODE == MODE_QKV) {
                    if (c < 192) { v0 *= SCALE_Q; v1 *= SCALE_Q; }
                    __half h0 = __float2half(v0), h1 = __float2half(v1);
                    *(__half2*)(Oh + (size_t)r * N + c) = __halves2half2(h0, h1);
                    *(__half2*)(Ol + (size_t)r * N + c) = __halves2half2(
                        __float2half(v0 - __half2float(h0)),
                        __float2half(v1 - __half2float(h1)));
                } else if (MODE == MODE_GELU_H) {
                    float g0 = 0.5f * v0 * (1.f + erff(v0 * 0.70710678118654752f));
                    float g1 = 0.5f * v1 * (1.f + erff(v1 * 0.70710678118654752f));
                    *(__half2*)(Oh + (size_t)r * N + c) =
                        __halves2half2(__float2half(g0), __float2half(g1));
                } else if (MODE == MODE_RESADD) {
                    float2* p = (float2*)(Cp + (size_t)r * N + c);
                    float2 o = *p; o.x += v0; o.y += v1; *p = o;
                } else { // MODE_PROJ
                    float2 rv = *(const float2*)(Rsrc + (size_t)dest * CC + c);
                    float2 o; o.x = rv.x + v0; o.y = rv.y + v1;
                    *(float2*)(Cp + (size_t)dest * CC + c) = o;
                }
            }
        }
    }
}

// ---------------------------------------------------------------------------
// Tensor-core windowed attention: one CTA = 2 heads (128 threads).
// Keeps full 3-term hi/lo precision for q,k,v; output written hi only.
// ---------------------------------------------------------------------------
struct __align__(16) AttnSmem2 {
    __half qh[2][2048], ql[2][2048];
    __half kh[2][2048], kl[2][2048];
    __half vh[2][2048], vl[2][2048];
    float  tbl[2][225];
    unsigned char rel[4096];
    int    rid[64];
};
#define ATTN_SMEM ((int)sizeof(AttnSmem2))

__global__ __launch_bounds__(128) void attn_mma(
    const __half* __restrict__ Qh, const __half* __restrict__ Ql,
    const float* __restrict__ tblg,
    __half* __restrict__ oh, int shift)
{
    extern __shared__ char smraw[];
    AttnSmem2& sm = *reinterpret_cast<AttnSmem2*>(smraw);
    int bw = blockIdx.y;
    int tid = threadIdx.x;
    int sub = tid >> 6, t64 = tid & 63;
    int lane = tid & 31, wq = (t64 >> 5);
    int head = blockIdx.x * 2 + sub;

    __half* bufs[6] = {sm.qh[sub], sm.ql[sub], sm.kh[sub], sm.kl[sub],
                       sm.vh[sub], sm.vl[sub]};
#pragma unroll
    for (int it = 0; it < 24; it++) {
        int idx = t64 + it * 64;
        int buf = idx >> 8, rem = idx & 255, r = rem >> 2, ch = rem & 3;
        int sec = buf >> 1;
        const __half* src = (buf & 1) ? Ql : Qh;
        const __half* p = src + (size_t)(bw * 64 + r) * QKVDIM + sec * 192 + head * 32 + ch * 8;
        uint4 val = *(const uint4*)p;
        *(uint4*)((char*)bufs[buf] + r * 64 + ((ch ^ (r & 3)) << 4)) = val;
    }
    for (int idx = tid; idx < 4096; idx += 128) {
        int n = idx >> 6, m = idx & 63;
        sm.rel[idx] = (unsigned char)(((n >> 3) - (m >> 3) + 7) * 15 + ((n & 7) - (m & 7) + 7));
    }
    for (int idx = t64; idx < 225; idx += 64) sm.tbl[sub][idx] = tblg[idx * NHEAD + head];
    if (tid < 64) {
        int wr = (bw >> 3) & 7, wc = bw & 7;
        int ti = tid >> 3, tj = tid & 7;
        int h = wr * 8 + ti, w = wc * 8 + tj;
        int rh = (h < 56) ? 0 : ((h < 60) ? 1 : 2);
        int rw = (w < 56) ? 0 : ((w < 60) ? 1 : 2);
        sm.rid[tid] = rh * 3 + rw;
    }
    __syncthreads();

    uint32_t qhb = smem_u32(sm.qh[sub]), qlb = smem_u32(sm.ql[sub]);
    uint32_t khb = smem_u32(sm.kh[sub]), klb = smem_u32(sm.kl[sub]);
    uint32_t vhb = smem_u32(sm.vh[sub]), vlb = smem_u32(sm.vl[sub]);

    float sc[2][8][4];
#pragma unroll
    for (int i = 0; i < 2; i++)
#pragma unroll
        for (int j = 0; j < 8; j++)
#pragma unroll
            for (int e = 0; e < 4; e++) sc[i][j][e] = 0.f;

#pragma unroll
    for (int kk = 0; kk < 2; kk++) {
        uint32_t aH[2][4], aL[2][4], bH[4][4], bL[4][4];
#pragma unroll
        for (int i = 0; i < 2; i++) {
            int r  = wq * 32 + i * 16 + (lane & 15);
            int ch = kk * 2 + (lane >> 4);
            uint32_t off = (uint32_t)(r * 64 + ((ch ^ (r & 3)) << 4));
            LDSM4(aH[i][0], aH[i][1], aH[i][2], aH[i][3], qhb + off);
            LDSM4(aL[i][0], aL[i][1], aL[i][2], aL[i][3], qlb + off);
        }
#pragma unroll
        for (int i = 0; i < 4; i++) {
            int grp = lane >> 3;
            int r  = i * 16 + ((grp >> 1) << 3) + (lane & 7);
            int ch = kk * 2 + (grp & 1);
            uint32_t off = (uint32_t)(r * 64 + ((ch ^ (r & 3)) << 4));
            LDSM4(bH[i][0], bH[i][1], bH[i][2], bH[i][3], khb + off);
            LDSM4(bL[i][0], bL[i][1], bL[i][2], bL[i][3], klb + off);
        }
#pragma unroll
        for (int i = 0; i < 2; i++)
#pragma unroll
            for (int j = 0; j < 8; j++) {
                int bi = j >> 1, bo = (j & 1) * 2;
                MMA16816(sc[i][j], aH[i], bH[bi][bo], bH[bi][bo + 1]);
            }
#pragma unroll
        for (int i = 0; i < 2; i++)
#pragma unroll
            for (int j = 0; j < 8; j++) {
                int bi = j >> 1, bo = (j & 1) * 2;
                MMA16816(sc[i][j], aH[i], bL[bi][bo], bL[bi][bo + 1]);
            }
#pragma unroll
        for (int i = 0; i < 2; i++)
#pragma unroll
            for (int j = 0; j < 8; j++) {
                int bi = j >> 1, bo = (j & 1) * 2;
                MMA16816(sc[i][j], aL[i], bH[bi][bo], bH[bi][bo + 1]);
            }
    }

    int gr = lane >> 2, lam = lane & 3;
    float invs[2][2];
#pragma unroll
    for (int i = 0; i < 2; i++) {
        int rA = wq * 32 + i * 16 + gr, rB = rA + 8;
        int ridA = sm.rid[rA], ridB = sm.rid[rB];
        float mxA = -1e30f, mxB = -1e30f;
#pragma unroll
        for (int j = 0; j < 8; j++) {
            int c0 = 8 * j + 2 * lam;
            float b00 = sm.tbl[sub][sm.rel[rA * 64 + c0]];
            float b01 = sm.tbl[sub][sm.rel[rA * 64 + c0 + 1]];
            float b10 = sm.tbl[sub][sm.rel[rB * 64 + c0]];
            float b11 = sm.tbl[sub][sm.rel[rB * 64 + c0 + 1]];
            if (shift) {
                int rc0 = sm.rid[c0], rc1 = sm.rid[c0 + 1];
                if (rc0 != ridA) b00 -= 100.f;
                if (rc1 != ridA) b01 -= 100.f;
                if (rc0 != ridB) b10 -= 100.f;
                if (rc1 != ridB) b11 -= 100.f;
            }
            sc[i][j][0] += b00; sc[i][j][1] += b01;
            sc[i][j][2] += b10; sc[i][j][3] += b11;
            mxA = fmaxf(mxA, fmaxf(sc[i][j][0], sc[i][j][1]));
            mxB = fmaxf(mxB, fmaxf(sc[i][j][2], sc[i][j][3]));
        }
        mxA = fmaxf(mxA, __shfl_xor_sync(0xffffffffu, mxA, 1));
        mxA = fmaxf(mxA, __shfl_xor_sync(0xffffffffu, mxA, 2));
        mxB = fmaxf(mxB, __shfl_xor_sync(0xffffffffu, mxB, 1));
        mxB = fmaxf(mxB, __shfl_xor_sync(0xffffffffu, mxB, 2));
        float sA = 0.f, sB = 0.f;
#pragma unroll
        for (int j = 0; j < 8; j++) {
            sc[i][j][0] = __expf(sc[i][j][0] - mxA); sA += sc[i][j][0];
            sc[i][j][1] = __expf(sc[i][j][1] - mxA); sA += sc[i][j][1];
            sc[i][j][2] = __expf(sc[i][j][2] - mxB); sB += sc[i][j][2];
            sc[i][j][3] = __expf(sc[i][j][3] - mxB); sB += sc[i][j][3];
        }
        sA += __shfl_xor_sync(0xffffffffu, sA, 1);
        sA += __shfl_xor_sync(0xffffffffu, sA, 2);
        sB += __shfl_xor_sync(0xffffffffu, sB, 1);
        sB += __shfl_xor_sync(0xffffffffu, sB, 2);
        invs[i][0] = 1.f / sA;
        invs[i][1] = 1.f / sB;
    }

    float out[2][4][4];
#pragma unroll
    for (int i = 0; i < 2; i++)
#pragma unroll
        for (int j = 0; j < 4; j++)
#pragma unroll
            for (int e = 0; e < 4; e++) out[i][j][e] = 0.f;

#pragma unroll
    for (int kv = 0; kv < 4; kv++) {
        uint32_t vH[2][4], vL[2][4];
#pragma unroll
        for (int dn = 0; dn < 2; dn++) {
            int r  = kv * 16 + (lane & 7) + (((lane >> 3) & 1) << 3);
            int ch = dn * 2 + (lane >> 4);
            uint32_t off = (uint32_t)(r * 64 + ((ch ^ (r & 3)) << 4));
            LDSM4T(vH[dn][0], vH[dn][1], vH[dn][2], vH[dn][3], vhb + off);
            LDSM4T(vL[dn][0], vL[dn][1], vL[dn][2], vL[dn][3], vlb + off);
        }
#pragma unroll
        for (int i = 0; i < 2; i++) {
            uint32_t pH[4], pL[4];
            pH[0] = pack_hi(sc[i][2 * kv][0], sc[i][2 * kv][1]);
            pH[1] = pack_hi(sc[i][2 * kv][2], sc[i][2 * kv][3]);
            pH[2] = pack_hi(sc[i][2 * kv + 1][0], sc[i][2 * kv + 1][1]);
            pH[3] = pack_hi(sc[i][2 * kv + 1][2], sc[i][2 * kv + 1][3]);
            pL[0] = pack_lo(sc[i][2 * kv][0], sc[i][2 * kv][1]);
            pL[1] = pack_lo(sc[i][2 * kv][2], sc[i][2 * kv][3]);
            pL[2] = pack_lo(sc[i][2 * kv + 1][0], sc[i][2 * kv + 1][1]);
            pL[3] = pack_lo(sc[i][2 * kv + 1][2], sc[i][2 * kv + 1][3]);
#pragma unroll
            for (int dt = 0; dt < 4; dt++) {
                int bi = dt >> 1, bo = (dt & 1) * 2;
                MMA16816(out[i][dt], pH, vH[bi][bo], vH[bi][bo + 1]);
            }
#pragma unroll
            for (int dt = 0; dt < 4; dt++) {
                int bi = dt >> 1, bo = (dt & 1) * 2;
                MMA16816(out[i][dt], pH, vL[bi][bo], vL[bi][bo + 1]);
            }
#pragma unroll
            for (int dt = 0; dt < 4; dt++) {
                int bi = dt >> 1, bo = (dt & 1) * 2;
                MMA16816(out[i][dt], pL, vH[bi][bo], vH[bi][bo + 1]);
            }
        }
    }

#pragma unroll
    for (int i = 0; i < 2; i++) {
        int rA = wq * 32 + i * 16 + gr;
#pragma unroll
        for (int hf = 0; hf < 2; hf++) {
            int r = rA + hf * 8;
            float inv = invs[i][hf];
            size_t base = (size_t)(bw * 64 + r) * 192 + head * 32;
#pragma unroll
            for (int dt = 0; dt < 4; dt++) {
                int c = 8 * dt + 2 * lam;
                float v0 = out[i][dt][hf * 2 + 0] * inv;
                float v1 = out[i][dt][hf * 2 + 1] * inv;
                *(__half2*)(oh + base + c) =
                    __halves2half2(__float2half(v0), __float2half(v1));
            }
        }
    }
}

// ---------------------------------------------------------------------------
// Launch
// ---------------------------------------------------------------------------
extern "C" void kernel_launch(void* const* d_in, const int* in_sizes, int n_in,
                              void* d_out, int out_size)
{
    const float* x    = (const float*)d_in[0];
    const float* n1g  = (const float*)d_in[1];
    const float* n1b  = (const float*)d_in[2];
    const float* qkvw = (const float*)d_in[3];
    const float* qkvb = (const float*)d_in[4];
    const float* tbl  = (const float*)d_in[5];
    const float* pw   = (const float*)d_in[6];
    const float* pb   = (const float*)d_in[7];
    const float* n2g  = (const float*)d_in[8];
    const float* n2b  = (const float*)d_in[9];
    const float* f1w  = (const float*)d_in[10];
    const float* f1b  = (const float*)d_in[11];
    const float* f2w  = (const float*)d_in[12];
    const float* f2b  = (const float*)d_in[13];
    float* xo = (float*)d_out;

    __half *ah, *bh, *bl, *wh, *wl;
    cudaGetSymbolAddress((void**)&ah,  g_ah);
    cudaGetSymbolAddress((void**)&bh,  g_bh);
    cudaGetSymbolAddress((void**)&bl,  g_bl);
    cudaGetSymbolAddress((void**)&wh,  g_wh);
    cudaGetSymbolAddress((void**)&wl,  g_wl);

    cudaFuncSetAttribute(gemm_mma<MODE_QKV>,    cudaFuncAttributeMaxDynamicSharedMemorySize, GEMM_SMEM);
    cudaFuncSetAttribute(gemm_mma<MODE_GELU_H>, cudaFuncAttributeMaxDynamicSharedMemorySize, GEMM_SMEM);
    cudaFuncSetAttribute(gemm_mma<MODE_RESADD>, cudaFuncAttributeMaxDynamicSharedMemorySize, GEMM_SMEM);
    cudaFuncSetAttribute(gemm_mma<MODE_PROJ>,   cudaFuncAttributeMaxDynamicSharedMemorySize, GEMM_SMEM);
    cudaFuncSetAttribute(attn_mma,              cudaFuncAttributeMaxDynamicSharedMemorySize, ATTN_SMEM);

    cvt2_kernel<<<(221184 + 73728 + 255) / 256, 256>>>(
        qkvw, wh + WOFF_QKV, wl + WOFF_QKV, 221184,
        pw,   wh + WOFF_PROJ, wl + WOFF_PROJ, 73728);
    cvt2_kernel<<<(294912 + 294912 + 255) / 256, 256>>>(
        f1w, wh + WOFF_FC1, wl + WOFF_FC1, 294912,
        f2w, wh + WOFF_FC2, wl + WOFF_FC2, 294912);

    for (int dep = 0; dep < 2; dep++) {
        int shift = dep ? 4 : 0;
        const float* resid = dep ? (const float*)xo : x;
        const float* lnsrc = dep ? (const float*)xo : x;
        const __half* wqh = wh + WOFF_QKV  + (size_t)dep * 110592;
        const __half* wql = wl + WOFF_QKV  + (size_t)dep * 110592;
        const __half* wph = wh + WOFF_PROJ + (size_t)dep * 36864;
        const __half* wpl = wl + WOFF_PROJ + (size_t)dep * 36864;
        const __half* w1h = wh + WOFF_FC1  + (size_t)dep * 147456;
        const __half* w1l = wl + WOFF_FC1  + (size_t)dep * 147456;
        const __half* w2h = wh + WOFF_FC2  + (size_t)dep * 147456;
        const __half* w2l = wl + WOFF_FC2  + (size_t)dep * 147456;

        // LN1 + shift + window partition -> ah (hi only)
        ln_kernel<<<MROWS / 8, 256>>>(lnsrc, n1g + dep * CC, n1b + dep * CC, ah, shift, 1);

        // QKV GEMM -> (bh, bl): hi+lo for attention, q pre-scaled
        gemm_mma<MODE_QKV><<<dim3(QKVDIM / 64, MROWS / 128), 256, GEMM_SMEM>>>(
            ah, wqh, wql, qkvb + dep * QKVDIM, nullptr, bh, bl, nullptr,
            QKVDIM, CC, 0);

        // Attention (full hi/lo precision) -> ah (hi only)
        attn_mma<<<dim3(NHEAD / 2, BATCH * NWIN), 128, ATTN_SMEM>>>(
            bh, bl, tbl + dep * 225 * NHEAD, ah, shift);

        // Proj GEMM + window reverse + residual(x or xo) -> xo
        gemm_mma<MODE_PROJ><<<dim3(CC / 64, MROWS / 128), 256, GEMM_SMEM>>>(
            ah, wph, wpl, pb + dep * CC, xo, nullptr, nullptr, resid,
            CC, CC, shift);

        // LN2 -> ah
        ln_kernel<<<MROWS / 8, 256>>>(xo, n2g + dep * CC, n2b + dep * CC, ah, 0, 0);

        // FC1 GEMM + GELU -> bh (hi only)
        gemm_mma<MODE_GELU_H><<<dim3(MLPDIM / 64, MROWS / 128), 256, GEMM_SMEM>>>(
            ah, w1h, w1l, f1b + dep * MLPDIM, nullptr, bh, nullptr, nullptr,
            MLPDIM, CC, 0);

        // FC2 GEMM + residual -> xo
        gemm_mma<MODE_RESADD><<<dim3(CC / 64, MROWS / 128), 256, GEMM_SMEM>>>(
            bh, w2h, w2l, f2b + dep * CC, xo, nullptr, nullptr, nullptr,
            CC, MLPDIM, 0);
    }
}

// round 14
// speedup vs baseline: 2.3063x; 1.1986x over previous
#include <cuda_runtime.h>
#include <cuda_fp16.h>
#include <cstdint>
#include <math.h>

// Problem constants
#define BATCH   16
#define CC      192
#define NHEAD   6
#define NTOK    64
#define NWIN    64
#define MROWS   65536
#define QKVDIM  576
#define MLPDIM  768
#define SCALE_Q 0.17677669529663687f

// Weight half-buffer offsets (elements)
#define WOFF_QKV  0
#define WOFF_PROJ 221184
#define WOFF_FC1  294912
#define WOFF_FC2  589824
#define WTOTAL    884736

// Scratch (device globals)
__device__ __half g_ah[(size_t)MROWS * 192];   // activations hi (GEMM A inputs)
__device__ __half g_bh[(size_t)MROWS * 768];   // qkv / gelu hi
__device__ __half g_bl[(size_t)MROWS * 768];   // qkv lo (attention only)
__device__ __half g_wh[WTOTAL];                // weights hi only

// ---------------------------------------------------------------------------
// PTX helpers
// ---------------------------------------------------------------------------
__device__ __forceinline__ uint32_t smem_u32(const void* p) {
    uint32_t a;
    asm("{ .reg .u64 t; cvta.to.shared.u64 t, %1; cvt.u32.u64 %0, t; }"
        : "=r"(a) : "l"(p));
    return a;
}

#define CP16(dst, src) \
    asm volatile("cp.async.cg.shared.global [%0], [%1], 16;" :: "r"(dst), "l"(src))

#define LDSM4(r0, r1, r2, r3, addr) \
    asm volatile("ldmatrix.sync.aligned.m8n8.x4.shared.b16 {%0,%1,%2,%3}, [%4];" \
        : "=r"(r0), "=r"(r1), "=r"(r2), "=r"(r3) : "r"(addr))

#define LDSM4T(r0, r1, r2, r3, addr) \
    asm volatile("ldmatrix.sync.aligned.m8n8.x4.trans.shared.b16 {%0,%1,%2,%3}, [%4];" \
        : "=r"(r0), "=r"(r1), "=r"(r2), "=r"(r3) : "r"(addr))

#define MMA16816(d, a, b0, b1) \
    asm volatile("mma.sync.aligned.m16n8k16.row.col.f32.f16.f16.f32 " \
        "{%0,%1,%2,%3},{%4,%5,%6,%7},{%8,%9},{%0,%1,%2,%3};" \
        : "+f"((d)[0]), "+f"((d)[1]), "+f"((d)[2]), "+f"((d)[3]) \
        : "r"((a)[0]), "r"((a)[1]), "r"((a)[2]), "r"((a)[3]), "r"(b0), "r"(b1))

__device__ __forceinline__ uint32_t pack_hi(float x, float y) {
    __half2 h = __halves2half2(__float2half(x), __float2half(y));
    return *(uint32_t*)&h;
}
__device__ __forceinline__ uint32_t pack_lo(float x, float y) {
    __half hx = __float2half(x), hy = __float2half(y);
    __half2 h = __halves2half2(__float2half(x - __half2float(hx)),
                               __float2half(y - __half2float(hy)));
    return *(uint32_t*)&h;
}

// ---------------------------------------------------------------------------
// Weight conversion: two fp32 arrays -> hi fp16 only
// ---------------------------------------------------------------------------
__global__ __launch_bounds__(256) void cvt2_kernel(
    const float* __restrict__ s1, __half* __restrict__ h1, int n1,
    const float* __restrict__ s2, __half* __restrict__ h2, int n2)
{
    int i = blockIdx.x * 256 + threadIdx.x;
    if (i < n1) h1[i] = __float2half(s1[i]);
    else if (i < n1 + n2) h2[i - n1] = __float2half(s2[i - n1]);
}

// ---------------------------------------------------------------------------
// LayerNorm (+ optional shift + window partition) -> fp16 hi only
// ---------------------------------------------------------------------------
__global__ __launch_bounds__(256) void ln_kernel(
    const float* __restrict__ x, const float* __restrict__ gam,
    const float* __restrict__ bet, __half* __restrict__ oh,
    int shift, int windowed)
{
    int warp = threadIdx.x >> 5, lane = threadIdx.x & 31;
    int r = blockIdx.x * 8 + warp;
    int src;
    if (windowed) {
        int bw = r >> 6, tok = r & 63;
        int b_img = bw >> 6, wr = (bw >> 3) & 7, wc = bw & 7;
        int ti = tok >> 3, tj = tok & 7;
        int h = (wr * 8 + ti + shift) & 63;
        int w = (wc * 8 + tj + shift) & 63;
        src = b_img * 4096 + h * 64 + w;
    } else src = r;
    const float* xp = x + (size_t)src * CC;
    float v[6];
    float s = 0.f;
#pragma unroll
    for (int j = 0; j < 6; j++) { v[j] = xp[lane + 32 * j]; s += v[j]; }
#pragma unroll
    for (int o = 16; o; o >>= 1) s += __shfl_xor_sync(0xffffffffu, s, o);
    float mu = s * (1.f / 192.f);
    float q = 0.f;
#pragma unroll
    for (int j = 0; j < 6; j++) { float d = v[j] - mu; q += d * d; }
#pragma unroll
    for (int o = 16; o; o >>= 1) q += __shfl_xor_sync(0xffffffffu, q, o);
    float rstd = rsqrtf(q * (1.f / 192.f) + 1e-5f);
    size_t base = (size_t)r * CC;
#pragma unroll
    for (int j = 0; j < 6; j++) {
        int c = lane + 32 * j;
        float y = (v[j] - mu) * rstd * gam[c] + bet[c];
        oh[base + c] = __float2half(y);
    }
}

// ---------------------------------------------------------------------------
// Pure fp16 tensor GEMM: C = A[M,K] @ W[N,K]^T + bias (1 MMA per k16).
// BM=128, BN=64, BK=64, 256 threads (8 warps, 4x2), warp tile 32x32.
// ---------------------------------------------------------------------------
#define MODE_QKV     0   // writes hi AND lo (attention consumes both)
#define MODE_GELU_H  1   // writes hi only
#define MODE_RESADD  2
#define MODE_PROJ    3

// stage: Ah 16K @0, Bh 8K @16384
#define STAGE_BYTES 24576
#define GEMM_SMEM   (2 * STAGE_BYTES)

__device__ __forceinline__ int proj_dest(int r, int shift) {
    int bw = r >> 6, tok = r & 63;
    int b_img = bw >> 6, wr = (bw >> 3) & 7, wc = bw & 7;
    int ti = tok >> 3, tj = tok & 7;
    int h = (wr * 8 + ti + shift) & 63;
    int w = (wc * 8 + tj + shift) & 63;
    return b_img * 4096 + h * 64 + w;
}

template<int MODE>
__global__ __launch_bounds__(256, 2) void gemm_mma(
    const __half* __restrict__ Ah,
    const __half* __restrict__ Bh,
    const float* __restrict__ bias, float* __restrict__ Cp,
    __half* __restrict__ Oh, __half* __restrict__ Ol,
    const float* __restrict__ Rsrc,
    int N, int K, int shift)
{
    extern __shared__ char smem[];
    const uint32_t smbase = smem_u32(smem);
    const int tid  = threadIdx.x;
    const int lane = tid & 31, warp = tid >> 5;
    const int wm = warp >> 1, wn = warp & 1;
    const int m0 = blockIdx.y * 128, n0 = blockIdx.x * 64;
    const int lc = tid & 7;
    const int lr = tid >> 3;

    const __half* pAh = Ah + (size_t)m0 * K + lc * 8;
    const __half* pBh = Bh + (size_t)n0 * K + lc * 8;

    const int niter = K >> 6;

    auto issue = [&](int s) {
        uint32_t sb = smbase + (uint32_t)(s & 1) * STAGE_BYTES;
        int k0 = s << 6;
#pragma unroll
        for (int i = 0; i < 4; i++) {
            int r = lr + 32 * i;
            uint32_t d = sb + r * 128 + ((uint32_t)(lc ^ (r & 7)) << 4);
            CP16(d, pAh + (size_t)r * K + k0);
        }
#pragma unroll
        for (int i = 0; i < 2; i++) {
            int r = lr + 32 * i;
            uint32_t d = sb + 16384 + r * 128 + ((uint32_t)(lc ^ (r & 7)) << 4);
            CP16(d, pBh + (size_t)r * K + k0);
        }
        asm volatile("cp.async.commit_group;");
    };

    float acc[2][4][4];
#pragma unroll
    for (int i = 0; i < 2; i++)
#pragma unroll
        for (int j = 0; j < 4; j++)
#pragma unroll
            for (int e = 0; e < 4; e++) acc[i][j][e] = 0.f;

    issue(0);
    for (int s = 0; s < niter; s++) {
        if (s + 1 < niter) {
            issue(s + 1);
            asm volatile("cp.async.wait_group 1;");
        } else {
            asm volatile("cp.async.wait_group 0;");
        }
        __syncthreads();
        uint32_t sb = smbase + (uint32_t)(s & 1) * STAGE_BYTES;
#pragma unroll
        for (int kk = 0; kk < 4; kk++) {
            uint32_t aH[2][4], bH[2][4];
#pragma unroll
            for (int i = 0; i < 2; i++) {
                int r  = wm * 32 + i * 16 + (lane & 15);
                int ch = kk * 2 + (lane >> 4);
                uint32_t ad = sb + r * 128 + ((uint32_t)(ch ^ (r & 7)) << 4);
                LDSM4(aH[i][0], aH[i][1], aH[i][2], aH[i][3], ad);
            }
#pragma unroll
            for (int i = 0; i < 2; i++) {
                int grp = lane >> 3;
                int r  = wn * 32 + i * 16 + ((grp >> 1) << 3) + (lane & 7);
                int ch = kk * 2 + (grp & 1);
                uint32_t bd = sb + 16384 + r * 128 + ((uint32_t)(ch ^ (r & 7)) << 4);
                LDSM4(bH[i][0], bH[i][1], bH[i][2], bH[i][3], bd);
            }
#pragma unroll
            for (int i = 0; i < 2; i++)
#pragma unroll
                for (int jj = 0; jj < 4; jj++) {
                    int bi = jj >> 1, bo = (jj & 1) * 2;
                    MMA16816(acc[i][jj], aH[i], bH[bi][bo], bH[bi][bo + 1]);
                }
        }
        __syncthreads();
    }

    // epilogue
#pragma unroll
    for (int i = 0; i < 2; i++) {
        int rb = m0 + wm * 32 + i * 16 + (lane >> 2);
#pragma unroll
        for (int hf = 0; hf < 2; hf++) {
            int r = rb + hf * 8;
            int dest = (MODE == MODE_PROJ) ? proj_dest(r, shift) : r;
#pragma unroll
            for (int jj = 0; jj < 4; jj++) {
                int c = n0 + wn * 32 + jj * 8 + (lane & 3) * 2;
                float v0 = acc[i][jj][hf * 2 + 0] + bias[c];
                float v1 = acc[i][jj][hf * 2 + 1] + bias[c + 1];
                if (MODE == MODE_QKV) {
                    if (c < 192) { v0 *= SCALE_Q; v1 *= SCALE_Q; }
                    __half h0 = __float2half(v0), h1 = __float2half(v1);
                    *(__half2*)(Oh + (size_t)r * N + c) = __halves2half2(h0, h1);
                    *(__half2*)(Ol + (size_t)r * N + c) = __halves2half2(
                        __float2half(v0 - __half2float(h0)),
                        __float2half(v1 - __half2float(h1)));
                } else if (MODE == MODE_GELU_H) {
                    float g0 = 0.5f * v0 * (1.f + erff(v0 * 0.70710678118654752f));
                    float g1 = 0.5f * v1 * (1.f + erff(v1 * 0.70710678118654752f));
                    *(__half2*)(Oh + (size_t)r * N + c) =
                        __halves2half2(__float2half(g0), __float2half(g1));
                } else if (MODE == MODE_RESADD) {
                    float2* p = (float2*)(Cp + (size_t)r * N + c);
                    float2 o = *p; o.x += v0; o.y += v1; *p = o;
                } else { // MODE_PROJ
                    float2 rv = *(const float2*)(Rsrc + (size_t)dest * CC + c);
                    float2 o; o.x = rv.x + v0; o.y = rv.y + v1;
                    *(float2*)(Cp + (size_t)dest * CC + c) = o;
                }
            }
        }
    }
}

// ---------------------------------------------------------------------------
// Tensor-core windowed attention: one CTA = 2 heads (128 threads).
// Full 3-term hi/lo precision for q,k,v; output hi only.
// ---------------------------------------------------------------------------
struct __align__(16) AttnSmem2 {
    __half qh[2][2048], ql[2][2048];
    __half kh[2][2048], kl[2][2048];
    __half vh[2][2048], vl[2][2048];
    float  tbl[2][225];
    unsigned char rel[4096];
    int    rid[64];
};
#define ATTN_SMEM ((int)sizeof(AttnSmem2))

__global__ __launch_bounds__(128) void attn_mma(
    const __half* __restrict__ Qh, const __half* __restrict__ Ql,
    const float* __restrict__ tblg,
    __half* __restrict__ oh, int shift)
{
    extern __shared__ char smraw[];
    AttnSmem2& sm = *reinterpret_cast<AttnSmem2*>(smraw);
    int bw = blockIdx.y;
    int tid = threadIdx.x;
    int sub = tid >> 6, t64 = tid & 63;
    int lane = tid & 31, wq = (t64 >> 5);
    int head = blockIdx.x * 2 + sub;

    __half* bufs[6] = {sm.qh[sub], sm.ql[sub], sm.kh[sub], sm.kl[sub],
                       sm.vh[sub], sm.vl[sub]};
#pragma unroll
    for (int it = 0; it < 24; it++) {
        int idx = t64 + it * 64;
        int buf = idx >> 8, rem = idx & 255, r = rem >> 2, ch = rem & 3;
        int sec = buf >> 1;
        const __half* src = (buf & 1) ? Ql : Qh;
        const __half* p = src + (size_t)(bw * 64 + r) * QKVDIM + sec * 192 + head * 32 + ch * 8;
        uint4 val = *(const uint4*)p;
        *(uint4*)((char*)bufs[buf] + r * 64 + ((ch ^ (r & 3)) << 4)) = val;
    }
    for (int idx = tid; idx < 4096; idx += 128) {
        int n = idx >> 6, m = idx & 63;
        sm.rel[idx] = (unsigned char)(((n >> 3) - (m >> 3) + 7) * 15 + ((n & 7) - (m & 7) + 7));
    }
    for (int idx = t64; idx < 225; idx += 64) sm.tbl[sub][idx] = tblg[idx * NHEAD + head];
    if (tid < 64) {
        int wr = (bw >> 3) & 7, wc = bw & 7;
        int ti = tid >> 3, tj = tid & 7;
        int h = wr * 8 + ti, w = wc * 8 + tj;
        int rh = (h < 56) ? 0 : ((h < 60) ? 1 : 2);
        int rw = (w < 56) ? 0 : ((w < 60) ? 1 : 2);
        sm.rid[tid] = rh * 3 + rw;
    }
    __syncthreads();

    uint32_t qhb = smem_u32(sm.qh[sub]), qlb = smem_u32(sm.ql[sub]);
    uint32_t khb = smem_u32(sm.kh[sub]), klb = smem_u32(sm.kl[sub]);
    uint32_t vhb = smem_u32(sm.vh[sub]), vlb = smem_u32(sm.vl[sub]);

    float sc[2][8][4];
#pragma unroll
    for (int i = 0; i < 2; i++)
#pragma unroll
        for (int j = 0; j < 8; j++)
#pragma unroll
            for (int e = 0; e < 4; e++) sc[i][j][e] = 0.f;

#pragma unroll
    for (int kk = 0; kk < 2; kk++) {
        uint32_t aH[2][4], aL[2][4], bH[4][4], bL[4][4];
#pragma unroll
        for (int i = 0; i < 2; i++) {
            int r  = wq * 32 + i * 16 + (lane & 15);
            int ch = kk * 2 + (lane >> 4);
            uint32_t off = (uint32_t)(r * 64 + ((ch ^ (r & 3)) << 4));
            LDSM4(aH[i][0], aH[i][1], aH[i][2], aH[i][3], qhb + off);
            LDSM4(aL[i][0], aL[i][1], aL[i][2], aL[i][3], qlb + off);
        }
#pragma unroll
        for (int i = 0; i < 4; i++) {
            int grp = lane >> 3;
            int r  = i * 16 + ((grp >> 1) << 3) + (lane & 7);
            int ch = kk * 2 + (grp & 1);
            uint32_t off = (uint32_t)(r * 64 + ((ch ^ (r & 3)) << 4));
            LDSM4(bH[i][0], bH[i][1], bH[i][2], bH[i][3], khb + off);
            LDSM4(bL[i][0], bL[i][1], bL[i][2], bL[i][3], klb + off);
        }
#pragma unroll
        for (int i = 0; i < 2; i++)
#pragma unroll
            for (int j = 0; j < 8; j++) {
                int bi = j >> 1, bo = (j & 1) * 2;
                MMA16816(sc[i][j], aH[i], bH[bi][bo], bH[bi][bo + 1]);
            }
#pragma unroll
        for (int i = 0; i < 2; i++)
#pragma unroll
            for (int j = 0; j < 8; j++) {
                int bi = j >> 1, bo = (j & 1) * 2;
                MMA16816(sc[i][j], aH[i], bL[bi][bo], bL[bi][bo + 1]);
            }
#pragma unroll
        for (int i = 0; i < 2; i++)
#pragma unroll
            for (int j = 0; j < 8; j++) {
                int bi = j >> 1, bo = (j & 1) * 2;
                MMA16816(sc[i][j], aL[i], bH[bi][bo], bH[bi][bo + 1]);
            }
    }

    int gr = lane >> 2, lam = lane & 3;
    float invs[2][2];
#pragma unroll
    for (int i = 0; i < 2; i++) {
        int rA = wq * 32 + i * 16 + gr, rB = rA + 8;
        int ridA = sm.rid[rA], ridB = sm.rid[rB];
        float mxA = -1e30f, mxB = -1e30f;
#pragma unroll
        for (int j = 0; j < 8; j++) {
            int c0 = 8 * j + 2 * lam;
            float b00 = sm.tbl[sub][sm.rel[rA * 64 + c0]];
            float b01 = sm.tbl[sub][sm.rel[rA * 64 + c0 + 1]];
            float b10 = sm.tbl[sub][sm.rel[rB * 64 + c0]];
            float b11 = sm.tbl[sub][sm.rel[rB * 64 + c0 + 1]];
            if (shift) {
                int rc0 = sm.rid[c0], rc1 = sm.rid[c0 + 1];
                if (rc0 != ridA) b00 -= 100.f;
                if (rc1 != ridA) b01 -= 100.f;
                if (rc0 != ridB) b10 -= 100.f;
                if (rc1 != ridB) b11 -= 100.f;
            }
            sc[i][j][0] += b00; sc[i][j][1] += b01;
            sc[i][j][2] += b10; sc[i][j][3] += b11;
            mxA = fmaxf(mxA, fmaxf(sc[i][j][0], sc[i][j][1]));
            mxB = fmaxf(mxB, fmaxf(sc[i][j][2], sc[i][j][3]));
        }
        mxA = fmaxf(mxA, __shfl_xor_sync(0xffffffffu, mxA, 1));
        mxA = fmaxf(mxA, __shfl_xor_sync(0xffffffffu, mxA, 2));
        mxB = fmaxf(mxB, __shfl_xor_sync(0xffffffffu, mxB, 1));
        mxB = fmaxf(mxB, __shfl_xor_sync(0xffffffffu, mxB, 2));
        float sA = 0.f, sB = 0.f;
#pragma unroll
        for (int j = 0; j < 8; j++) {
            sc[i][j][0] = __expf(sc[i][j][0] - mxA); sA += sc[i][j][0];
            sc[i][j][1] = __expf(sc[i][j][1] - mxA); sA += sc[i][j][1];
            sc[i][j][2] = __expf(sc[i][j][2] - mxB); sB += sc[i][j][2];
            sc[i][j][3] = __expf(sc[i][j][3] - mxB); sB += sc[i][j][3];
        }
        sA += __shfl_xor_sync(0xffffffffu, sA, 1);
        sA += __shfl_xor_sync(0xffffffffu, sA, 2);
        sB += __shfl_xor_sync(0xffffffffu, sB, 1);
        sB += __shfl_xor_sync(0xffffffffu, sB, 2);
        invs[i][0] = 1.f / sA;
        invs[i][1] = 1.f / sB;
    }

    float out[2][4][4];
#pragma unroll
    for (int i = 0; i < 2; i++)
#pragma unroll
        for (int j = 0; j < 4; j++)
#pragma unroll
            for (int e = 0; e < 4; e++) out[i][j][e] = 0.f;

#pragma unroll
    for (int kv = 0; kv < 4; kv++) {
        uint32_t vH[2][4], vL[2][4];
#pragma unroll
        for (int dn = 0; dn < 2; dn++) {
            int r  = kv * 16 + (lane & 7) + (((lane >> 3) & 1) << 3);
            int ch = dn * 2 + (lane >> 4);
            uint32_t off = (uint32_t)(r * 64 + ((ch ^ (r & 3)) << 4));
            LDSM4T(vH[dn][0], vH[dn][1], vH[dn][2], vH[dn][3], vhb + off);
            LDSM4T(vL[dn][0], vL[dn][1], vL[dn][2], vL[dn][3], vlb + off);
        }
#pragma unroll
        for (int i = 0; i < 2; i++) {
            uint32_t pH[4], pL[4];
            pH[0] = pack_hi(sc[i][2 * kv][0], sc[i][2 * kv][1]);
            pH[1] = pack_hi(sc[i][2 * kv][2], sc[i][2 * kv][3]);
            pH[2] = pack_hi(sc[i][2 * kv + 1][0], sc[i][2 * kv + 1][1]);
            pH[3] = pack_hi(sc[i][2 * kv + 1][2], sc[i][2 * kv + 1][3]);
            pL[0] = pack_lo(sc[i][2 * kv][0], sc[i][2 * kv][1]);
            pL[1] = pack_lo(sc[i][2 * kv][2], sc[i][2 * kv][3]);
            pL[2] = pack_lo(sc[i][2 * kv + 1][0], sc[i][2 * kv + 1][1]);
            pL[3] = pack_lo(sc[i][2 * kv + 1][2], sc[i][2 * kv + 1][3]);
#pragma unroll
            for (int dt = 0; dt < 4; dt++) {
                int bi = dt >> 1, bo = (dt & 1) * 2;
                MMA16816(out[i][dt], pH, vH[bi][bo], vH[bi][bo + 1]);
            }
#pragma unroll
            for (int dt = 0; dt < 4; dt++) {
                int bi = dt >> 1, bo = (dt & 1) * 2;
                MMA16816(out[i][dt], pH, vL[bi][bo], vL[bi][bo + 1]);
            }
#pragma unroll
            for (int dt = 0; dt < 4; dt++) {
                int bi = dt >> 1, bo = (dt & 1) * 2;
                MMA16816(out[i][dt], pL, vH[bi][bo], vH[bi][bo + 1]);
            }
        }
    }

#pragma unroll
    for (int i = 0; i < 2; i++) {
        int rA = wq * 32 + i * 16 + gr;
#pragma unroll
        for (int hf = 0; hf < 2; hf++) {
            int r = rA + hf * 8;
            float inv = invs[i][hf];
            size_t base = (size_t)(bw * 64 + r) * 192 + head * 32;
#pragma unroll
            for (int dt = 0; dt < 4; dt++) {
                int c = 8 * dt + 2 * lam;
                float v0 = out[i][dt][hf * 2 + 0] * inv;
                float v1 = out[i][dt][hf * 2 + 1] * inv;
                *(__half2*)(oh + base + c) =
                    __halves2half2(__float2half(v0), __float2half(v1));
            }
        }
    }
}

// ---------------------------------------------------------------------------
// Launch
// ---------------------------------------------------------------------------
extern "C" void kernel_launch(void* const* d_in, const int* in_sizes, int n_in,
                              void* d_out, int out_size)
{
    const float* x    = (const float*)d_in[0];
    const float* n1g  = (const float*)d_in[1];
    const float* n1b  = (const float*)d_in[2];
    const float* qkvw = (const float*)d_in[3];
    const float* qkvb = (const float*)d_in[4];
    const float* tbl  = (const float*)d_in[5];
    const float* pw   = (const float*)d_in[6];
    const float* pb   = (const float*)d_in[7];
    const float* n2g  = (const float*)d_in[8];
    const float* n2b  = (const float*)d_in[9];
    const float* f1w  = (const float*)d_in[10];
    const float* f1b  = (const float*)d_in[11];
    const float* f2w  = (const float*)d_in[12];
    const float* f2b  = (const float*)d_in[13];
    float* xo = (float*)d_out;

    __half *ah, *bh, *bl, *wh;
    cudaGetSymbolAddress((void**)&ah, g_ah);
    cudaGetSymbolAddress((void**)&bh, g_bh);
    cudaGetSymbolAddress((void**)&bl, g_bl);
    cudaGetSymbolAddress((void**)&wh, g_wh);

    cudaFuncSetAttribute(gemm_mma<MODE_QKV>,    cudaFuncAttributeMaxDynamicSharedMemorySize, GEMM_SMEM);
    cudaFuncSetAttribute(gemm_mma<MODE_GELU_H>, cudaFuncAttributeMaxDynamicSharedMemorySize, GEMM_SMEM);
    cudaFuncSetAttribute(gemm_mma<MODE_RESADD>, cudaFuncAttributeMaxDynamicSharedMemorySize, GEMM_SMEM);
    cudaFuncSetAttribute(gemm_mma<MODE_PROJ>,   cudaFuncAttributeMaxDynamicSharedMemorySize, GEMM_SMEM);
    cudaFuncSetAttribute(attn_mma,              cudaFuncAttributeMaxDynamicSharedMemorySize, ATTN_SMEM);

    cvt2_kernel<<<(221184 + 73728 + 255) / 256, 256>>>(
        qkvw, wh + WOFF_QKV, 221184, pw, wh + WOFF_PROJ, 73728);
    cvt2_kernel<<<(294912 + 294912 + 255) / 256, 256>>>(
        f1w, wh + WOFF_FC1, 294912, f2w, wh + WOFF_FC2, 294912);

    for (int dep = 0; dep < 2; dep++) {
        int shift = dep ? 4 : 0;
        const float* resid = dep ? (const float*)xo : x;
        const float* lnsrc = dep ? (const float*)xo : x;
        const __half* wqh = wh + WOFF_QKV  + (size_t)dep * 110592;
        const __half* wph = wh + WOFF_PROJ + (size_t)dep * 36864;
        const __half* w1h = wh + WOFF_FC1  + (size_t)dep * 147456;
        const __half* w2h = wh + WOFF_FC2  + (size_t)dep * 147456;

        // LN1 + shift + window partition -> ah (hi only)
        ln_kernel<<<MROWS / 8, 256>>>(lnsrc, n1g + dep * CC, n1b + dep * CC, ah, shift, 1);

        // QKV GEMM -> (bh, bl): hi+lo for attention, q pre-scaled
        gemm_mma<MODE_QKV><<<dim3(QKVDIM / 64, MROWS / 128), 256, GEMM_SMEM>>>(
            ah, wqh, qkvb + dep * QKVDIM, nullptr, bh, bl, nullptr,
            QKVDIM, CC, 0);

        // Attention (full hi/lo precision) -> ah (hi only)
        attn_mma<<<dim3(NHEAD / 2, BATCH * NWIN), 128, ATTN_SMEM>>>(
            bh, bl, tbl + dep * 225 * NHEAD, ah, shift);

        // Proj GEMM + window reverse + residual(x or xo) -> xo
        gemm_mma<MODE_PROJ><<<dim3(CC / 64, MROWS / 128), 256, GEMM_SMEM>>>(
            ah, wph, pb + dep * CC, xo, nullptr, nullptr, resid,
            CC, CC, shift);

        // LN2 -> ah
        ln_kernel<<<MROWS / 8, 256>>>(xo, n2g + dep * CC, n2b + dep * CC, ah, 0, 0);

        // FC1 GEMM + GELU -> bh (hi only)
        gemm_mma<MODE_GELU_H><<<dim3(MLPDIM / 64, MROWS / 128), 256, GEMM_SMEM>>>(
            ah, w1h, f1b + dep * MLPDIM, nullptr, bh, nullptr, nullptr,
            MLPDIM, CC, 0);

        // FC2 GEMM + residual -> xo
        gemm_mma<MODE_RESADD><<<dim3(CC / 64, MROWS / 128), 256, GEMM_SMEM>>>(
            bh, w2h, f2b + dep * CC, xo, nullptr, nullptr, nullptr,
            CC, MLPDIM, 0);
    }
}